// round 15
// baseline (speedup 1.0000x reference)
#include <cuda_runtime.h>
#include <cuda_fp16.h>
#include <stdint.h>

#define D 128
#define NMAX 50048
#define EMAX 1000000
#define SCAN_ELEMS 1024              // elements per scan block (256 thr x 4)
#define SCAN_MAXBLK 64

// Scratch (__device__ globals — allocation-free rule)
__device__ __half g_h[NMAX * D];     // h = x @ W^T + b (fp16 storage)
__device__ float g_dis[NMAX];        // (deg+1)^-0.5
__device__ int   g_degi[NMAX];       // edge count per source
__device__ int   g_cnt[NMAX];        // edge count per target
__device__ int   g_off[NMAX + 1];    // CSR offsets (by target)
__device__ int   g_cur[NMAX];        // fill cursors
__device__ int   g_src[EMAX];        // CSR payload: source index per edge
__device__ int   g_bsum[SCAN_MAXBLK];

// ---------------------------------------------------------------------------
// 4 edges per thread: independent atomic chains overlap their latency
__global__ void k_count(const int* __restrict__ ei, int E) {
    int base = (blockIdx.x * blockDim.x + threadIdx.x) * 4;
#pragma unroll
    for (int u = 0; u < 4; u++) {
        int e = base + u;
        if (e < E) {
            atomicAdd(&g_degi[ei[e]], 1);
            atomicAdd(&g_cnt[ei[E + e]], 1);
        }
    }
}

// --- scan phase 1: per-block sums; also computes g_dis ---------------------
__global__ void k_scan1(int n) {
    __shared__ int wsum[8];
    int t = threadIdx.x;
    int base = blockIdx.x * SCAN_ELEMS + t * 4;
    int s = 0;
#pragma unroll
    for (int u = 0; u < 4; u++) {
        int i = base + u;
        if (i < n) {
            s += g_cnt[i];
            g_dis[i] = rsqrtf((float)(g_degi[i] + 1));  // fused dis
        }
    }
#pragma unroll
    for (int o = 16; o; o >>= 1) s += __shfl_xor_sync(0xffffffffu, s, o);
    if ((t & 31) == 0) wsum[t >> 5] = s;
    __syncthreads();
    if (t == 0) {
        int tot = 0;
#pragma unroll
        for (int w = 0; w < 8; w++) tot += wsum[w];
        g_bsum[blockIdx.x] = tot;
    }
}

// --- scan phase 2 (fused): intra-block scan + inline block-offset scan -----
__global__ void k_scan3(int nb, int n) {
    __shared__ int tsum[256];
    __shared__ int woff[8];
    __shared__ int bsum_s[SCAN_MAXBLK];
    __shared__ int blk_off_s;
    int t = threadIdx.x;
    int base = blockIdx.x * SCAN_ELEMS + t * 4;

    if (t < SCAN_MAXBLK) bsum_s[t] = (t < nb) ? g_bsum[t] : 0;

    int v[4];
    int s = 0;
#pragma unroll
    for (int u = 0; u < 4; u++) {
        int i = base + u;
        v[u] = (i < n) ? g_cnt[i] : 0;
        s += v[u];
    }
    int lane = t & 31, wid = t >> 5;
    int inc = s;
#pragma unroll
    for (int o = 1; o < 32; o <<= 1) {
        int p = __shfl_up_sync(0xffffffffu, inc, o);
        if (lane >= o) inc += p;
    }
    if (lane == 31) tsum[wid] = inc;
    __syncthreads();
    if (t == 0) {
        // serial exclusive prefix of block sums (<=64 values, smem-resident)
        int acc = 0;
        for (int i = 0; i < nb; i++) {
            if (i == (int)blockIdx.x) blk_off_s = acc;
            acc += bsum_s[i];
        }
        if (blockIdx.x == 0) g_off[n] = acc;  // total = E (+/- none)
    }
    if (t < 8) {
        int wv = tsum[t];
        int wi = wv;
#pragma unroll
        for (int o = 1; o < 8; o <<= 1) {
            int p = __shfl_up_sync(0xffu, wi, o);
            if (t >= o) wi += p;
        }
        woff[t] = wi - wv;
    }
    __syncthreads();

    int excl = blk_off_s + woff[wid] + (inc - s);
#pragma unroll
    for (int u = 0; u < 4; u++) {
        int i = base + u;
        if (i < n) {
            g_off[i] = excl;
            g_cur[i] = excl;
            excl += v[u];
        }
    }
}

// 4 edges per thread: overlap atomic-return latency
__global__ void k_fill(const int* __restrict__ ei, int E) {
    int base = (blockIdx.x * blockDim.x + threadIdx.x) * 4;
    int r[4], pos[4];
#pragma unroll
    for (int u = 0; u < 4; u++) {
        int e = base + u;
        if (e < E) {
            r[u] = ei[e];
            pos[u] = atomicAdd(&g_cur[ei[E + e]], 1);
        }
    }
#pragma unroll
    for (int u = 0; u < 4; u++) {
        int e = base + u;
        if (e < E) g_src[pos[u]] = r[u];
    }
}

// ---------------------------------------------------------------------------
// fp16 mma.sync GEMM (m16n8k16): g_h[r][c] = fp16( sum_k x[r][k]*W[c][k] + b[c] )
// fp16 smem tiles (~70 KB total) -> 2 CTAs/SM at full 128-row tile.
// 512 threads = 16 warps, warp grid 4(m) x 4(n): 32 rows x 32 cols per warp.
// ---------------------------------------------------------------------------
#define XPADH 136                    // halves per row (272B: +4-bank row skew)
#define SM_HALVES (2 * 128 * XPADH)  // two tiles
#define SM_BYTES  (SM_HALVES * 2 + 128 * 4)

#define MMA_F16(cc, a0, a1, a2, a3, b0, b1)                                \
    asm volatile(                                                          \
        "mma.sync.aligned.m16n8k16.row.col.f32.f16.f16.f32 "               \
        "{%0,%1,%2,%3}, {%4,%5,%6,%7}, {%8,%9}, {%0,%1,%2,%3};"            \
        : "+f"(cc[0]), "+f"(cc[1]), "+f"(cc[2]), "+f"(cc[3])               \
        : "r"(a0), "r"(a1), "r"(a2), "r"(a3), "r"(b0), "r"(b1))

__global__ __launch_bounds__(512, 2)
void k_gemm(const float* __restrict__ x, const float* __restrict__ W,
            const float* __restrict__ bias, int n) {
    extern __shared__ __half smh[];
    __half* ws  = smh;                     // [128][XPADH] W (fp16)
    __half* xs  = smh + 128 * XPADH;       // [128][XPADH] x tile (fp16)
    float*  b_s = (float*)(smh + SM_HALVES);  // [128]

    int t = threadIdx.x;
    int w = t >> 5;
    int lane = t & 31;
    int g  = lane >> 2;     // group id 0..7
    int tg = lane & 3;      // thread-in-group 0..3
    int mw = w & 3;         // warp row-group (32 rows)
    int nw = w >> 2;        // warp col-group (32 cols)
    int row0 = blockIdx.x * 128;

    for (int i = t; i < 4096; i += 512) {
        int r  = i >> 5;
        int k4 = (i & 31) * 4;
        float4 v = *(const float4*)&W[r * D + k4];
        __half2* dst = (__half2*)&ws[r * XPADH + k4];
        dst[0] = __floats2half2_rn(v.x, v.y);
        dst[1] = __floats2half2_rn(v.z, v.w);
    }
    for (int i = t; i < 4096; i += 512) {
        int r  = i >> 5;
        int k4 = (i & 31) * 4;
        int row = row0 + r;
        float4 v = make_float4(0.f, 0.f, 0.f, 0.f);
        if (row < n) v = *(const float4*)&x[row * D + k4];
        __half2* dst = (__half2*)&xs[r * XPADH + k4];
        dst[0] = __floats2half2_rn(v.x, v.y);
        dst[1] = __floats2half2_rn(v.z, v.w);
    }
    if (t < 128) b_s[t] = bias[t];
    __syncthreads();

    float c[2][4][4];
#pragma unroll
    for (int mi = 0; mi < 2; mi++)
#pragma unroll
        for (int ni = 0; ni < 4; ni++)
#pragma unroll
            for (int j = 0; j < 4; j++) c[mi][ni][j] = 0.f;

    const __half* xbase = &xs[(mw * 32) * XPADH];
    const __half* wbase = &ws[(nw * 32) * XPADH];

#pragma unroll
    for (int k0 = 0; k0 < 128; k0 += 16) {
        uint32_t a[2][4];
#pragma unroll
        for (int mi = 0; mi < 2; mi++) {
            const __half* ab = &xbase[(mi * 16) * XPADH + k0 + 2 * tg];
            a[mi][0] = *(const uint32_t*)&ab[g * XPADH];
            a[mi][1] = *(const uint32_t*)&ab[(g + 8) * XPADH];
            a[mi][2] = *(const uint32_t*)&ab[g * XPADH + 8];
            a[mi][3] = *(const uint32_t*)&ab[(g + 8) * XPADH + 8];
        }
#pragma unroll
        for (int ni = 0; ni < 4; ni++) {
            const __half* bb = &wbase[(ni * 8 + g) * XPADH + k0 + 2 * tg];
            uint32_t b0 = *(const uint32_t*)&bb[0];
            uint32_t b1 = *(const uint32_t*)&bb[8];
            MMA_F16(c[0][ni], a[0][0], a[0][1], a[0][2], a[0][3], b0, b1);
            MMA_F16(c[1][ni], a[1][0], a[1][1], a[1][2], a[1][3], b0, b1);
        }
    }

#pragma unroll
    for (int mi = 0; mi < 2; mi++) {
#pragma unroll
        for (int ni = 0; ni < 4; ni++) {
            int lr  = mw * 32 + mi * 16 + g;
            int col = nw * 32 + ni * 8 + tg * 2;
            float bv0 = b_s[col], bv1 = b_s[col + 1];
            int row = row0 + lr;
            if (row < n) {
                *(__half2*)&g_h[row * D + col] =
                    __floats2half2_rn(c[mi][ni][0] + bv0, c[mi][ni][1] + bv1);
            }
            int row2 = row0 + lr + 8;
            if (row2 < n) {
                *(__half2*)&g_h[row2 * D + col] =
                    __floats2half2_rn(c[mi][ni][2] + bv0, c[mi][ni][3] + bv1);
            }
        }
    }
}

// ---------------------------------------------------------------------------
// Fused gather + self-loop + ReLU + LayerNorm + residual. Warp per node.
__global__ void k_agg(const float* __restrict__ x,
                      const float* __restrict__ gamma,
                      const float* __restrict__ beta,
                      float* __restrict__ out, int n) {
    int node = (blockIdx.x * blockDim.x + threadIdx.x) >> 5;
    int lane = threadIdx.x & 31;
    if (node >= n) return;

    float dc = g_dis[node];
    int lo = g_off[node], hi = g_off[node + 1];
    int l4 = lane * 4;

    float4 acc = make_float4(0.f, 0.f, 0.f, 0.f);
    for (int i = lo; i < hi; i++) {
        int r = g_src[i];
        float dr = g_dis[r];
        uint2 raw = *(const uint2*)&g_h[r * D + l4];
        float2 f0 = __half22float2(*(__half2*)&raw.x);
        float2 f1 = __half22float2(*(__half2*)&raw.y);
        acc.x += dr * f0.x; acc.y += dr * f0.y;
        acc.z += dr * f1.x; acc.w += dr * f1.y;
    }
    {
        uint2 raw = *(const uint2*)&g_h[node * D + l4];
        float2 f0 = __half22float2(*(__half2*)&raw.x);
        float2 f1 = __half22float2(*(__half2*)&raw.y);
        acc.x += dc * f0.x; acc.y += dc * f0.y;
        acc.z += dc * f1.x; acc.w += dc * f1.y;
    }

    float4 v;
    v.x = fmaxf(acc.x * dc, 0.f);
    v.y = fmaxf(acc.y * dc, 0.f);
    v.z = fmaxf(acc.z * dc, 0.f);
    v.w = fmaxf(acc.w * dc, 0.f);

    float s  = v.x + v.y + v.z + v.w;
    float ss = v.x * v.x + v.y * v.y + v.z * v.z + v.w * v.w;
#pragma unroll
    for (int o = 16; o; o >>= 1) {
        s  += __shfl_xor_sync(0xffffffffu, s,  o);
        ss += __shfl_xor_sync(0xffffffffu, ss, o);
    }
    float mu  = s * (1.f / 128.f);
    float var = ss * (1.f / 128.f) - mu * mu;
    float inv = rsqrtf(var + 1e-5f);

    float4 g  = *(const float4*)&gamma[l4];
    float4 be = *(const float4*)&beta[l4];
    float4 xv = *(const float4*)&x[node * D + l4];

    float4 o;
    o.x = (v.x - mu) * inv * g.x + be.x + xv.x;
    o.y = (v.y - mu) * inv * g.y + be.y + xv.y;
    o.z = (v.z - mu) * inv * g.z + be.z + xv.z;
    o.w = (v.w - mu) * inv * g.w + be.w + xv.w;
    *(float4*)&out[node * D + l4] = o;
}

// ---------------------------------------------------------------------------
extern "C" void kernel_launch(void* const* d_in, const int* in_sizes, int n_in,
                              void* d_out, int out_size) {
    const float* x     = (const float*)d_in[0];
    const int*   ei    = (const int*)d_in[1];
    const float* W     = (const float*)d_in[2];
    const float* b     = (const float*)d_in[3];
    const float* gamma = (const float*)d_in[4];
    const float* beta  = (const float*)d_in[5];
    float*       out   = (float*)d_out;

    int n = in_sizes[0] / D;
    int E = in_sizes[1] / 2;
    int nb = (n + SCAN_ELEMS - 1) / SCAN_ELEMS;
    int eb4 = (E + 1023) / 1024;     // 4 edges/thread blocks

    static cudaStream_t s2 = nullptr;
    static cudaEvent_t evFork = nullptr, evJoin = nullptr;
    static void *p_degi = nullptr, *p_cnt = nullptr;
    if (s2 == nullptr) {
        cudaStreamCreateWithFlags(&s2, cudaStreamNonBlocking);
        cudaEventCreateWithFlags(&evFork, cudaEventDisableTiming);
        cudaEventCreateWithFlags(&evJoin, cudaEventDisableTiming);
        cudaGetSymbolAddress(&p_degi, g_degi);
        cudaGetSymbolAddress(&p_cnt, g_cnt);
    }

    // Fork: branch B (CSR build) on s2, branch A (gemm) on default stream.
    cudaEventRecord(evFork, 0);
    cudaStreamWaitEvent(s2, evFork, 0);

    cudaMemsetAsync(p_degi, 0, (size_t)n * sizeof(int), s2);
    cudaMemsetAsync(p_cnt,  0, (size_t)n * sizeof(int), s2);
    k_count<<<eb4, 256, 0, s2>>>(ei, E);
    k_scan1<<<nb, 256, 0, s2>>>(n);          // block sums + g_dis
    k_scan3<<<nb, 256, 0, s2>>>(nb, n);      // offsets (inline block-scan)
    k_fill <<<eb4, 256, 0, s2>>>(ei, E);
    cudaEventRecord(evJoin, s2);

    cudaFuncSetAttribute(k_gemm, cudaFuncAttributeMaxDynamicSharedMemorySize, SM_BYTES);
    k_gemm<<<(n + 127) / 128, 512, SM_BYTES>>>(x, W, b, n);

    // Join, then fused aggregation epilogue.
    cudaStreamWaitEvent(0, evJoin, 0);
    k_agg<<<(n + 7) / 8, 256>>>(x, gamma, beta, out, n);
}

// round 16
// speedup vs baseline: 1.0673x; 1.0673x over previous
#include <cuda_runtime.h>
#include <cuda_fp16.h>
#include <stdint.h>

#define D 128
#define NMAX 50048
#define EMAX 1000000
#define SCAN_ELEMS 1024              // elements per scan block (256 thr x 4)
#define SCAN_MAXBLK 64

// Scratch (__device__ globals — allocation-free rule)
__device__ __half g_h[NMAX * D];     // h = x @ W^T + b (fp16 storage)
__device__ float g_dis[NMAX];        // (deg+1)^-0.5
__device__ int   g_degi[NMAX];       // edge count per source
__device__ int   g_cnt[NMAX];        // edge count per target
__device__ int   g_off[NMAX + 1];    // CSR offsets (by target)
__device__ int   g_src[EMAX];        // CSR payload: source index per edge
__device__ int   g_rank[EMAX];       // per-edge rank within its target
__device__ int   g_bsum[SCAN_MAXBLK];
__device__ int   g_boff[SCAN_MAXBLK];

// ---------------------------------------------------------------------------
__global__ void k_zero(int n) {
    int i = blockIdx.x * blockDim.x + threadIdx.x;
    if (i < n) { g_degi[i] = 0; g_cnt[i] = 0; }
}

// 4 edges per thread. The cnt atomic's return value IS the edge's rank
// within its target bucket -> stored for an atomic-free k_fill.
__global__ void k_count(const int* __restrict__ ei, int E) {
    int base = (blockIdx.x * blockDim.x + threadIdx.x) * 4;
#pragma unroll
    for (int u = 0; u < 4; u++) {
        int e = base + u;
        if (e < E) {
            atomicAdd(&g_degi[ei[e]], 1);
            g_rank[e] = atomicAdd(&g_cnt[ei[E + e]], 1);
        }
    }
}

// --- parallel exclusive scan; phase 1 also computes g_dis ------------------
__global__ void k_scan1(int n) {
    __shared__ int wsum[8];
    int t = threadIdx.x;
    int base = blockIdx.x * SCAN_ELEMS + t * 4;
    int s = 0;
#pragma unroll
    for (int u = 0; u < 4; u++) {
        int i = base + u;
        if (i < n) {
            s += g_cnt[i];
            g_dis[i] = rsqrtf((float)(g_degi[i] + 1));  // fused dis
        }
    }
#pragma unroll
    for (int o = 16; o; o >>= 1) s += __shfl_xor_sync(0xffffffffu, s, o);
    if ((t & 31) == 0) wsum[t >> 5] = s;
    __syncthreads();
    if (t == 0) {
        int tot = 0;
#pragma unroll
        for (int w = 0; w < 8; w++) tot += wsum[w];
        g_bsum[blockIdx.x] = tot;
    }
}

__global__ void k_scan2(int nb, int n) {
    __shared__ int sh[SCAN_MAXBLK];
    int t = threadIdx.x;
    int v = (t < nb) ? g_bsum[t] : 0;
    sh[t] = v;
    __syncthreads();
    for (int o = 1; o < SCAN_MAXBLK; o <<= 1) {
        int p = (t >= o) ? sh[t - o] : 0;
        __syncthreads();
        sh[t] += p;
        __syncthreads();
    }
    if (t < nb) g_boff[t] = sh[t] - v;
    if (t == SCAN_MAXBLK - 1) g_off[n] = sh[t];
}

__global__ void k_scan3(int n) {
    __shared__ int tsum[256];
    __shared__ int woff[8];
    int t = threadIdx.x;
    int base = blockIdx.x * SCAN_ELEMS + t * 4;

    int v[4];
    int s = 0;
#pragma unroll
    for (int u = 0; u < 4; u++) {
        int i = base + u;
        v[u] = (i < n) ? g_cnt[i] : 0;
        s += v[u];
    }
    int lane = t & 31, wid = t >> 5;
    int inc = s;
#pragma unroll
    for (int o = 1; o < 32; o <<= 1) {
        int p = __shfl_up_sync(0xffffffffu, inc, o);
        if (lane >= o) inc += p;
    }
    if (lane == 31) tsum[wid] = inc;
    __syncthreads();
    if (t < 8) {
        int wv = tsum[t];
        int wi = wv;
#pragma unroll
        for (int o = 1; o < 8; o <<= 1) {
            int p = __shfl_up_sync(0xffu, wi, o);
            if (t >= o) wi += p;
        }
        woff[t] = wi - wv;
    }
    __syncthreads();

    int excl = g_boff[blockIdx.x] + woff[wid] + (inc - s);
#pragma unroll
    for (int u = 0; u < 4; u++) {
        int i = base + u;
        if (i < n) {
            g_off[i] = excl;
            excl += v[u];
        }
    }
}

// Atomic-free fill: pos = g_off[target] + precomputed rank.
__global__ void k_fill(const int* __restrict__ ei, int E) {
    int base = (blockIdx.x * blockDim.x + threadIdx.x) * 4;
    int r[4], pos[4];
#pragma unroll
    for (int u = 0; u < 4; u++) {
        int e = base + u;
        if (e < E) {
            r[u] = ei[e];
            pos[u] = g_off[ei[E + e]] + g_rank[e];
        }
    }
#pragma unroll
    for (int u = 0; u < 4; u++) {
        int e = base + u;
        if (e < E) g_src[pos[u]] = r[u];
    }
}

// ---------------------------------------------------------------------------
// fp16 mma.sync GEMM (m16n8k16): g_h[r][c] = fp16( sum_k x[r][k]*W[c][k] + b[c] )
// fp16 smem tiles (~70 KB total) -> 2 CTAs/SM at full 128-row tile.
// 512 threads = 16 warps, warp grid 4(m) x 4(n): 32 rows x 32 cols per warp.
// ---------------------------------------------------------------------------
#define XPADH 136                    // halves per row (272B: +4-bank row skew)
#define SM_HALVES (2 * 128 * XPADH)  // two tiles
#define SM_BYTES  (SM_HALVES * 2 + 128 * 4)

#define MMA_F16(cc, a0, a1, a2, a3, b0, b1)                                \
    asm volatile(                                                          \
        "mma.sync.aligned.m16n8k16.row.col.f32.f16.f16.f32 "               \
        "{%0,%1,%2,%3}, {%4,%5,%6,%7}, {%8,%9}, {%0,%1,%2,%3};"            \
        : "+f"(cc[0]), "+f"(cc[1]), "+f"(cc[2]), "+f"(cc[3])               \
        : "r"(a0), "r"(a1), "r"(a2), "r"(a3), "r"(b0), "r"(b1))

__global__ __launch_bounds__(512, 2)
void k_gemm(const float* __restrict__ x, const float* __restrict__ W,
            const float* __restrict__ bias, int n) {
    extern __shared__ __half smh[];
    __half* ws  = smh;                     // [128][XPADH] W (fp16)
    __half* xs  = smh + 128 * XPADH;       // [128][XPADH] x tile (fp16)
    float*  b_s = (float*)(smh + SM_HALVES);  // [128]

    int t = threadIdx.x;
    int w = t >> 5;
    int lane = t & 31;
    int g  = lane >> 2;     // group id 0..7
    int tg = lane & 3;      // thread-in-group 0..3
    int mw = w & 3;         // warp row-group (32 rows)
    int nw = w >> 2;        // warp col-group (32 cols)
    int row0 = blockIdx.x * 128;

    for (int i = t; i < 4096; i += 512) {
        int r  = i >> 5;
        int k4 = (i & 31) * 4;
        float4 v = *(const float4*)&W[r * D + k4];
        __half2* dst = (__half2*)&ws[r * XPADH + k4];
        dst[0] = __floats2half2_rn(v.x, v.y);
        dst[1] = __floats2half2_rn(v.z, v.w);
    }
    for (int i = t; i < 4096; i += 512) {
        int r  = i >> 5;
        int k4 = (i & 31) * 4;
        int row = row0 + r;
        float4 v = make_float4(0.f, 0.f, 0.f, 0.f);
        if (row < n) v = *(const float4*)&x[row * D + k4];
        __half2* dst = (__half2*)&xs[r * XPADH + k4];
        dst[0] = __floats2half2_rn(v.x, v.y);
        dst[1] = __floats2half2_rn(v.z, v.w);
    }
    if (t < 128) b_s[t] = bias[t];
    __syncthreads();

    float c[2][4][4];
#pragma unroll
    for (int mi = 0; mi < 2; mi++)
#pragma unroll
        for (int ni = 0; ni < 4; ni++)
#pragma unroll
            for (int j = 0; j < 4; j++) c[mi][ni][j] = 0.f;

    const __half* xbase = &xs[(mw * 32) * XPADH];
    const __half* wbase = &ws[(nw * 32) * XPADH];

#pragma unroll
    for (int k0 = 0; k0 < 128; k0 += 16) {
        uint32_t a[2][4];
#pragma unroll
        for (int mi = 0; mi < 2; mi++) {
            const __half* ab = &xbase[(mi * 16) * XPADH + k0 + 2 * tg];
            a[mi][0] = *(const uint32_t*)&ab[g * XPADH];
            a[mi][1] = *(const uint32_t*)&ab[(g + 8) * XPADH];
            a[mi][2] = *(const uint32_t*)&ab[g * XPADH + 8];
            a[mi][3] = *(const uint32_t*)&ab[(g + 8) * XPADH + 8];
        }
#pragma unroll
        for (int ni = 0; ni < 4; ni++) {
            const __half* bb = &wbase[(ni * 8 + g) * XPADH + k0 + 2 * tg];
            uint32_t b0 = *(const uint32_t*)&bb[0];
            uint32_t b1 = *(const uint32_t*)&bb[8];
            MMA_F16(c[0][ni], a[0][0], a[0][1], a[0][2], a[0][3], b0, b1);
            MMA_F16(c[1][ni], a[1][0], a[1][1], a[1][2], a[1][3], b0, b1);
        }
    }

#pragma unroll
    for (int mi = 0; mi < 2; mi++) {
#pragma unroll
        for (int ni = 0; ni < 4; ni++) {
            int lr  = mw * 32 + mi * 16 + g;
            int col = nw * 32 + ni * 8 + tg * 2;
            float bv0 = b_s[col], bv1 = b_s[col + 1];
            int row = row0 + lr;
            if (row < n) {
                *(__half2*)&g_h[row * D + col] =
                    __floats2half2_rn(c[mi][ni][0] + bv0, c[mi][ni][1] + bv1);
            }
            int row2 = row0 + lr + 8;
            if (row2 < n) {
                *(__half2*)&g_h[row2 * D + col] =
                    __floats2half2_rn(c[mi][ni][2] + bv0, c[mi][ni][3] + bv1);
            }
        }
    }
}

// ---------------------------------------------------------------------------
// Fused gather + self-loop + ReLU + LayerNorm + residual. Warp per node.
__global__ void k_agg(const float* __restrict__ x,
                      const float* __restrict__ gamma,
                      const float* __restrict__ beta,
                      float* __restrict__ out, int n) {
    int node = (blockIdx.x * blockDim.x + threadIdx.x) >> 5;
    int lane = threadIdx.x & 31;
    if (node >= n) return;

    float dc = g_dis[node];
    int lo = g_off[node], hi = g_off[node + 1];
    int l4 = lane * 4;

    float4 acc = make_float4(0.f, 0.f, 0.f, 0.f);
    for (int i = lo; i < hi; i++) {
        int r = g_src[i];
        float dr = g_dis[r];
        uint2 raw = *(const uint2*)&g_h[r * D + l4];
        float2 f0 = __half22float2(*(__half2*)&raw.x);
        float2 f1 = __half22float2(*(__half2*)&raw.y);
        acc.x += dr * f0.x; acc.y += dr * f0.y;
        acc.z += dr * f1.x; acc.w += dr * f1.y;
    }
    {
        uint2 raw = *(const uint2*)&g_h[node * D + l4];
        float2 f0 = __half22float2(*(__half2*)&raw.x);
        float2 f1 = __half22float2(*(__half2*)&raw.y);
        acc.x += dc * f0.x; acc.y += dc * f0.y;
        acc.z += dc * f1.x; acc.w += dc * f1.y;
    }

    float4 v;
    v.x = fmaxf(acc.x * dc, 0.f);
    v.y = fmaxf(acc.y * dc, 0.f);
    v.z = fmaxf(acc.z * dc, 0.f);
    v.w = fmaxf(acc.w * dc, 0.f);

    float s  = v.x + v.y + v.z + v.w;
    float ss = v.x * v.x + v.y * v.y + v.z * v.z + v.w * v.w;
#pragma unroll
    for (int o = 16; o; o >>= 1) {
        s  += __shfl_xor_sync(0xffffffffu, s,  o);
        ss += __shfl_xor_sync(0xffffffffu, ss, o);
    }
    float mu  = s * (1.f / 128.f);
    float var = ss * (1.f / 128.f) - mu * mu;
    float inv = rsqrtf(var + 1e-5f);

    float4 g  = *(const float4*)&gamma[l4];
    float4 be = *(const float4*)&beta[l4];
    float4 xv = *(const float4*)&x[node * D + l4];

    float4 o;
    o.x = (v.x - mu) * inv * g.x + be.x + xv.x;
    o.y = (v.y - mu) * inv * g.y + be.y + xv.y;
    o.z = (v.z - mu) * inv * g.z + be.z + xv.z;
    o.w = (v.w - mu) * inv * g.w + be.w + xv.w;
    *(float4*)&out[node * D + l4] = o;
}

// ---------------------------------------------------------------------------
extern "C" void kernel_launch(void* const* d_in, const int* in_sizes, int n_in,
                              void* d_out, int out_size) {
    const float* x     = (const float*)d_in[0];
    const int*   ei    = (const int*)d_in[1];
    const float* W     = (const float*)d_in[2];
    const float* b     = (const float*)d_in[3];
    const float* gamma = (const float*)d_in[4];
    const float* beta  = (const float*)d_in[5];
    float*       out   = (float*)d_out;

    int n = in_sizes[0] / D;
    int E = in_sizes[1] / 2;
    int nb = (n + SCAN_ELEMS - 1) / SCAN_ELEMS;
    int eb4 = (E + 1023) / 1024;     // 4 edges/thread blocks

    static cudaStream_t s2 = nullptr;
    static cudaEvent_t evFork = nullptr, evJoin = nullptr;
    if (s2 == nullptr) {
        cudaStreamCreateWithFlags(&s2, cudaStreamNonBlocking);
        cudaEventCreateWithFlags(&evFork, cudaEventDisableTiming);
        cudaEventCreateWithFlags(&evJoin, cudaEventDisableTiming);
    }

    // Fork: branch B (CSR build) on s2, branch A (gemm) on default stream.
    cudaEventRecord(evFork, 0);
    cudaStreamWaitEvent(s2, evFork, 0);

    k_zero <<<(n + 255) / 256, 256, 0, s2>>>(n);
    k_count<<<eb4, 256, 0, s2>>>(ei, E);
    k_scan1<<<nb, 256, 0, s2>>>(n);          // block sums + g_dis
    k_scan2<<<1, SCAN_MAXBLK, 0, s2>>>(nb, n);
    k_scan3<<<nb, 256, 0, s2>>>(n);
    k_fill <<<eb4, 256, 0, s2>>>(ei, E);
    cudaEventRecord(evJoin, s2);

    cudaFuncSetAttribute(k_gemm, cudaFuncAttributeMaxDynamicSharedMemorySize, SM_BYTES);
    k_gemm<<<(n + 127) / 128, 512, SM_BYTES>>>(x, W, b, n);

    // Join, then fused aggregation epilogue.
    cudaStreamWaitEvent(0, evJoin, 0);
    k_agg<<<(n + 7) / 8, 256>>>(x, gamma, beta, out, n);
}